// round 8
// baseline (speedup 1.0000x reference)
#include <cuda_runtime.h>
#include <cuda_bf16.h>
#include <stdint.h>

#define P_PTS   10000
#define NPTS    100
#define MAXB    4096
#define NCHUNK  20            // ceil(10000/512)

typedef unsigned long long ull;

// ------------------------------ scratch ------------------------------------
__device__ float g_phi [MAXB * 300];   // phi row-major [b][300]
__device__ float g_W1t [304 * 128];    // W1 transposed [k][c]
__device__ float g_Wct [256 * 256];    // [W3|W4] transposed [k][j]
__device__ float g_b34 [256];          // b3 + b4

// ------------------------------ f32x2 helpers -------------------------------
union F4U2 { float4 f4; ull u2[2]; float f[4]; };

__device__ __forceinline__ ull dup2(float a) {
    ull r; asm("mov.b64 %0, {%1, %1};" : "=l"(r) : "f"(a)); return r;
}
__device__ __forceinline__ void ffma2(ull& acc, ull a, ull b) {
    asm("fma.rn.f32x2 %0, %1, %2, %3;" : "=l"(acc) : "l"(a), "l"(b), "l"(acc));
}
__device__ __forceinline__ float2 unpack2(ull v) {
    float2 f; asm("mov.b64 {%0, %1}, %2;" : "=f"(f.x), "=f"(f.y) : "l"(v)); return f;
}

// ------------------------------ foveate (+ folded prep) ---------------------
// CTA-per-batch, 512 threads, 512-pt chunks (1 pt/thread), depth-2 register
// prefetch (DRAM latency hidden behind the ballot/scan of current chunk),
// single ballot per warp, ONE sync per chunk, early exit at 100 points.
// phi stored ROW-MAJOR (coalesced); the GEMM transposes in smem.
__device__ __forceinline__ void fv_load(const float* xb, int it, int tid, float* v) {
    int p = it * 512 + tid;
    if (p < P_PTS) {
        v[0] = xb[p];
        v[1] = xb[P_PTS + p];
        v[2] = xb[2 * P_PTS + p];
    } else {
        v[0] = 1.0e30f; v[1] = 1.0e30f; v[2] = 1.0e30f;   // never in-box
    }
}

__global__ void __launch_bounds__(512) foveate_kernel(
        const float* __restrict__ x,  const float* __restrict__ lt,
        const float* __restrict__ W1, const float* __restrict__ W3,
        const float* __restrict__ W4, const float* __restrict__ b3,
        const float* __restrict__ b4) {
    __shared__ float s0[NPTS], s1[NPTS], s2[NPTS];
    __shared__ int warp_cnt[2][16];

    int b = blockIdx.x;
    int tid = threadIdx.x, lane = tid & 31, wid = tid >> 5;

    // ---- folded prep: coalesced reads, scattered (non-stalling) writes ----
    {
        int g = b * 512 + tid;
        if (g < 300 * 128) {
            int c = g / 300, k = g - c * 300;
            g_W1t[k * 128 + c] = W1[g];
        }
        if (g < 256 * 128) {
            int j = g >> 7, k = g & 127;
            g_Wct[k * 256 + j]         = W3[g];
            g_Wct[(128 + k) * 256 + j] = W4[g];
        }
        if (g < 256) g_b34[g] = b3[g] + b4[g];
    }

    const float* xb = x + (size_t)b * (3 * P_PTS);
    float l0 = lt[b * 3 + 0], l1 = lt[b * 3 + 1], l2 = lt[b * 3 + 2];
    float lo0 = l0 - 0.25f, hi0 = l0 + 0.25f;
    float lo1 = l1 - 0.25f, hi1 = l1 + 0.25f;
    float lo2 = l2 - 0.25f, hi2 = l2 + 0.25f;
    unsigned ltm = (1u << lane) - 1u;

    float bufv[2][3], nx[3];
    fv_load(xb, 0, tid, bufv[0]);
    fv_load(xb, 1, tid, bufv[1]);

    int run = 0, pb = 0;
    for (int it = 0; it < NCHUNK; it++) {
        bool have = (it + 2 < NCHUNK);
        if (have) fv_load(xb, it + 2, tid, nx);   // prefetch (overlaps scan)

        float* V = bufv[it & 1];
        float v0 = V[0], v1 = V[1], v2 = V[2];
        bool in = (v0 >= lo0) && (v0 <= hi0) &&
                  (v1 >= lo1) && (v1 <= hi1) &&
                  (v2 >= lo2) && (v2 <= hi2);

        unsigned bl = __ballot_sync(0xffffffffu, in);
        if (lane == 0) warp_cnt[pb][wid] = __popc(bl);
        int excl = __popc(bl & ltm);
        __syncthreads();

        int woff = 0, tot = 0;
#pragma unroll
        for (int w = 0; w < 16; w++) {
            int v = warp_cnt[pb][w];
            tot += v;
            if (w < wid) woff += v;
        }
        if (in) {
            int r = run + woff + excl;
            if (r < NPTS) { s0[r] = v0; s1[r] = v1; s2[r] = v2; }
        }
        run += tot;                 // identical across CTA -> uniform break
        pb ^= 1;
        if (run >= NPTS) break;
        if (have) { V[0] = nx[0]; V[1] = nx[1]; V[2] = nx[2]; }
    }
    __syncthreads();                // scatter visible to all

    int n = run;
    if (tid < 300) {
        int axis = tid / 100, pos = tid - axis * 100;
        float v = 0.0f;
        if (n > 0) {
            int j = (n >= NPTS) ? pos : (pos % n);
            v = (axis == 0) ? s0[j] : ((axis == 1) ? s1[j] : s2[j]);
        }
        g_phi[(size_t)b * 300 + tid] = v;   // coalesced row-major
    }
}

// ------------------------------ fused MLP -----------------------------------
// BM=8 rows per CTA, 128 threads, grid B/8 = 512 -> single wave, ~5 CTAs/SM.
// Phase 1: hA[c][r] = relu(phi @ W1^T + b1) (c<128), relu(l @ W2^T + b2) (c>=128)
//          thread tile: 8 rows (4 f32x2 pairs, A smem-broadcast) x 1 col.
// Phase 2: out = relu(hA^T @ Wc^T + b34), Wct double-buffered, 8 rows x 2 cols.
#define HA_STRIDE 12

__global__ void __launch_bounds__(128) mlp_kernel(
        const float* __restrict__ lt, const float* __restrict__ b1,
        const float* __restrict__ W2, const float* __restrict__ b2,
        float* __restrict__ out) {
    __shared__ __align__(16) float pool[8192];   // ph1: phiAs(2400)+w1Bs(2x2560)=7520
                                                 // ph2: wctBs(2x4096)=8192 (aliased)
    __shared__ __align__(16) float hA[256 * HA_STRIDE];
    __shared__ float ls[24];

    float* phiAs = pool;            // [k*8 + r], k < 300
    float* w1Bs  = pool + 2400;     // [2][20*128]
    float* wctBs = pool;            // [2][16*256]

    int row0 = blockIdx.x * 8;
    int tid = threadIdx.x;

    // ---- phase 1 staging: load phi row-major, transpose into smem ----
    for (int idx = tid; idx < 600; idx += 128) {     // 75 float4 per row x 8 rows
        int r = idx / 75, k4 = idx - r * 75;
        float4 v = *(const float4*)&g_phi[(size_t)(row0 + r) * 300 + k4 * 4];
        phiAs[(k4 * 4 + 0) * 8 + r] = v.x;
        phiAs[(k4 * 4 + 1) * 8 + r] = v.y;
        phiAs[(k4 * 4 + 2) * 8 + r] = v.z;
        phiAs[(k4 * 4 + 3) * 8 + r] = v.w;
    }
    if (tid < 24) ls[tid] = lt[row0 * 3 + tid];
#pragma unroll
    for (int j = 0; j < 5; j++) {                    // W1 tile 0 (640 float4)
        int idx = tid + j * 128;
        *(float4*)&w1Bs[idx * 4] = *(const float4*)&g_W1t[idx * 4];
    }

    int c0 = tid;                   // phase-1 column (0..127)
    ull acc[4];
    {
        ull bini = dup2(b1[c0]);
#pragma unroll
        for (int p = 0; p < 4; p++) acc[p] = bini;
    }

    // ---- phase 1 mainloop: 15 K-tiles of 20 ----
    for (int kt = 0; kt < 15; kt++) {
        __syncthreads();
        float4 pw[5];
        if (kt + 1 < 15) {
            const float* src = g_W1t + (kt + 1) * 2560;
#pragma unroll
            for (int j = 0; j < 5; j++) pw[j] = *(const float4*)(src + (tid + j * 128) * 4);
        }
        const float* Bc = w1Bs + (kt & 1) * 2560;
        int k0 = kt * 20;
#pragma unroll
        for (int kk = 0; kk < 20; kk++) {
            int k = k0 + kk;
            F4U2 a0, a1;
            a0.f4 = *(const float4*)&phiAs[k * 8];       // rows 0..3 (broadcast)
            a1.f4 = *(const float4*)&phiAs[k * 8 + 4];   // rows 4..7
            ull d = dup2(Bc[kk * 128 + c0]);
            ffma2(acc[0], a0.u2[0], d);
            ffma2(acc[1], a0.u2[1], d);
            ffma2(acc[2], a1.u2[0], d);
            ffma2(acc[3], a1.u2[1], d);
        }
        if (kt + 1 < 15) {
            float* dst = w1Bs + ((kt + 1) & 1) * 2560;
#pragma unroll
            for (int j = 0; j < 5; j++) *(float4*)(dst + (tid + j * 128) * 4) = pw[j];
        }
    }

    // ---- phase 1 epilogue: transposed h into hA ----
#pragma unroll
    for (int p = 0; p < 4; p++) {
        float2 v = unpack2(acc[p]);
        hA[c0 * HA_STRIDE + 2 * p    ] = fmaxf(v.x, 0.0f);
        hA[c0 * HA_STRIDE + 2 * p + 1] = fmaxf(v.y, 0.0f);
    }
    {   // l_out: col (128+tid), 8 rows
        int c = tid;
        float w0 = W2[c * 3 + 0], w1 = W2[c * 3 + 1], w2 = W2[c * 3 + 2];
        float bc = b2[c];
#pragma unroll
        for (int r = 0; r < 8; r++) {
            float v = bc + ls[r * 3 + 0] * w0 + ls[r * 3 + 1] * w1 + ls[r * 3 + 2] * w2;
            hA[(128 + c) * HA_STRIDE + r] = fmaxf(v, 0.0f);
        }
    }
    __syncthreads();                // pool reads done + hA complete -> alias pool

    // ---- phase 2 staging: Wct tile 0 (16x256 = 1024 float4) ----
#pragma unroll
    for (int j = 0; j < 8; j++) {
        int idx = tid + j * 128;
        *(float4*)&wctBs[idx * 4] = *(const float4*)&g_Wct[idx * 4];
    }

    int c2 = tid * 2;               // phase-2 column pair (0..254)
    ull acc2[4][2];
#pragma unroll
    for (int p = 0; p < 4; p++) {
        acc2[p][0] = dup2(g_b34[c2]);
        acc2[p][1] = dup2(g_b34[c2 + 1]);
    }

    // ---- phase 2 mainloop: 16 K-tiles of 16 ----
    for (int kt = 0; kt < 16; kt++) {
        __syncthreads();
        float4 pw[8];
        if (kt + 1 < 16) {
            const float* src = g_Wct + (kt + 1) * 4096;
#pragma unroll
            for (int j = 0; j < 8; j++) pw[j] = *(const float4*)(src + (tid + j * 128) * 4);
        }
        const float* Bc = wctBs + (kt & 1) * 4096;
        int k0 = kt * 16;
#pragma unroll
        for (int kk = 0; kk < 16; kk++) {
            int k = k0 + kk;
            F4U2 a0, a1;
            a0.f4 = *(const float4*)&hA[k * HA_STRIDE];       // broadcast
            a1.f4 = *(const float4*)&hA[k * HA_STRIDE + 4];
            float2 w = *(const float2*)&wctBs[(kt & 1) * 4096 + kk * 256 + c2];
            ull d0 = dup2(w.x), d1 = dup2(w.y);
            ffma2(acc2[0][0], a0.u2[0], d0); ffma2(acc2[0][1], a0.u2[0], d1);
            ffma2(acc2[1][0], a0.u2[1], d0); ffma2(acc2[1][1], a0.u2[1], d1);
            ffma2(acc2[2][0], a1.u2[0], d0); ffma2(acc2[2][1], a1.u2[0], d1);
            ffma2(acc2[3][0], a1.u2[1], d0); ffma2(acc2[3][1], a1.u2[1], d1);
        }
        if (kt + 1 < 16) {
            float* dst = wctBs + ((kt + 1) & 1) * 4096;
#pragma unroll
            for (int j = 0; j < 8; j++) *(float4*)(dst + (tid + j * 128) * 4) = pw[j];
        }
        (void)Bc;
    }

    // ---- phase 2 epilogue: coalesced float2 stores ----
#pragma unroll
    for (int p = 0; p < 4; p++) {
        float2 va = unpack2(acc2[p][0]);   // col c2,   rows 2p / 2p+1
        float2 vb = unpack2(acc2[p][1]);   // col c2+1, rows 2p / 2p+1
        float2 o0 = make_float2(fmaxf(va.x, 0.f), fmaxf(vb.x, 0.f));
        float2 o1 = make_float2(fmaxf(va.y, 0.f), fmaxf(vb.y, 0.f));
        size_t base = (size_t)(row0 + 2 * p) * 256 + c2;
        *(float2*)&out[base]       = o0;
        *(float2*)&out[base + 256] = o1;
    }
}

// ------------------------------ launch --------------------------------------
extern "C" void kernel_launch(void* const* d_in, const int* in_sizes, int n_in,
                              void* d_out, int out_size) {
    const float* x  = (const float*)d_in[0];
    const float* lt = (const float*)d_in[1];
    const float* W1 = (const float*)d_in[2];
    const float* b1 = (const float*)d_in[3];
    const float* W2 = (const float*)d_in[4];
    const float* b2 = (const float*)d_in[5];
    const float* W3 = (const float*)d_in[6];
    const float* b3 = (const float*)d_in[7];
    const float* W4 = (const float*)d_in[8];
    const float* b4 = (const float*)d_in[9];
    float* out = (float*)d_out;

    int B = in_sizes[0] / (3 * P_PTS);
    if (B > MAXB) B = MAXB;

    foveate_kernel<<<B, 512>>>(x, lt, W1, W3, W4, b3, b4);
    mlp_kernel<<<B / 8, 128>>>(lt, b1, W2, b2, out);
}

// round 10
// speedup vs baseline: 1.3224x; 1.3224x over previous
#include <cuda_runtime.h>
#include <cuda_bf16.h>
#include <stdint.h>

#define P_PTS   10000
#define NPTS    100
#define MAXB    4096
#define HS      20            // transposed-activation smem stride (multiple of 4!)

typedef unsigned long long ull;

// ------------------------------ scratch ------------------------------------
__device__ float g_phi [MAXB * 300];   // phi row-major [b][300]
__device__ float g_h   [MAXB * 256];   // hidden concat row-major [b][256]
__device__ float g_W1t [300 * 128];    // W1 transposed [k][c]
__device__ float g_Wct [256 * 256];    // [W3|W4] transposed [k][j]
__device__ float g_b34 [256];          // b3 + b4

// ------------------------------ f32x2 helpers -------------------------------
union F4U2 { float4 f4; ull u2[2]; float f[4]; };

__device__ __forceinline__ ull dup2(float a) {
    ull r; asm("mov.b64 %0, {%1, %1};" : "=l"(r) : "f"(a)); return r;
}
__device__ __forceinline__ void ffma2(ull& acc, ull a, ull b) {
    asm("fma.rn.f32x2 %0, %1, %2, %3;" : "=l"(acc) : "l"(a), "l"(b), "l"(acc));
}
__device__ __forceinline__ float2 unpack2(ull v) {
    float2 f; asm("mov.b64 {%0, %1}, %2;" : "=f"(f.x), "=f"(f.y) : "l"(v)); return f;
}

// ------------------------------ foveate (+ folded prep) ---------------------
// R5-proven: CTA-per-batch, 512 threads, 2048-pt float4 chunks, ballot-based
// ordered compaction, ONE __syncthreads per chunk, early exit at 100 points.
__global__ void __launch_bounds__(512) foveate_kernel(
        const float* __restrict__ x,  const float* __restrict__ lt,
        const float* __restrict__ W1, const float* __restrict__ W3,
        const float* __restrict__ W4, const float* __restrict__ b3,
        const float* __restrict__ b4) {
    __shared__ float s0[NPTS], s1[NPTS], s2[NPTS];
    __shared__ int warp_cnt[2][16];

    int b = blockIdx.x;
    int tid = threadIdx.x, lane = tid & 31, wid = tid >> 5;

    // folded prep (independent; consumed by GEMMs)
    {
        int g = b * 512 + tid;
        if (g < 300 * 128) {
            int k = g / 128, c = g - k * 128;
            g_W1t[g] = W1[c * 300 + k];
        }
        if (g < 256 * 256) {
            int k = g >> 8, j = g & 255;
            g_Wct[g] = (k < 128) ? W3[j * 128 + k] : W4[j * 128 + (k - 128)];
        }
        if (g < 256) g_b34[g] = b3[g] + b4[g];
    }

    const float* xb = x + (size_t)b * 3 * P_PTS;
    float l0 = lt[b * 3 + 0], l1 = lt[b * 3 + 1], l2 = lt[b * 3 + 2];
    float lo0 = l0 - 0.25f, hi0 = l0 + 0.25f;
    float lo1 = l1 - 0.25f, hi1 = l1 + 0.25f;
    float lo2 = l2 - 0.25f, hi2 = l2 + 0.25f;
    unsigned ltm = (1u << lane) - 1u;

    int run = 0, buf = 0;
    for (int base = 0; base < P_PTS; base += 2048) {
        int p0 = base + tid * 4;
        float v0[4], v1[4], v2[4];
        unsigned m = 0;
        if (p0 < P_PTS) {  // P divisible by 4 -> float4 fully in or out
            float4 f0 = *(const float4*)(xb + p0);
            float4 f1 = *(const float4*)(xb + P_PTS + p0);
            float4 f2 = *(const float4*)(xb + 2 * P_PTS + p0);
            v0[0]=f0.x; v0[1]=f0.y; v0[2]=f0.z; v0[3]=f0.w;
            v1[0]=f1.x; v1[1]=f1.y; v1[2]=f1.z; v1[3]=f1.w;
            v2[0]=f2.x; v2[1]=f2.y; v2[2]=f2.z; v2[3]=f2.w;
#pragma unroll
            for (int i = 0; i < 4; i++) {
                bool in = (v0[i] >= lo0) && (v0[i] <= hi0) &&
                          (v1[i] >= lo1) && (v1[i] <= hi1) &&
                          (v2[i] >= lo2) && (v2[i] <= hi2);
                m |= ((unsigned)in) << i;
            }
        }
        unsigned bl0 = __ballot_sync(0xffffffffu,  m       & 1u);
        unsigned bl1 = __ballot_sync(0xffffffffu, (m >> 1) & 1u);
        unsigned bl2 = __ballot_sync(0xffffffffu, (m >> 2) & 1u);
        unsigned bl3 = __ballot_sync(0xffffffffu, (m >> 3) & 1u);
        if (lane == 0)
            warp_cnt[buf][wid] = __popc(bl0) + __popc(bl1) + __popc(bl2) + __popc(bl3);
        int excl = __popc(bl0 & ltm) + __popc(bl1 & ltm) +
                   __popc(bl2 & ltm) + __popc(bl3 & ltm);
        __syncthreads();

        int woff = 0, tot = 0;
#pragma unroll
        for (int w = 0; w < 16; w++) {
            int v = warp_cnt[buf][w];
            tot += v;
            if (w < wid) woff += v;
        }
        int r = run + woff + excl;
#pragma unroll
        for (int i = 0; i < 4; i++) {
            if ((m >> i) & 1u) {
                if (r < NPTS) { s0[r] = v0[i]; s1[r] = v1[i]; s2[r] = v2[i]; }
                r++;
            }
        }
        run += tot;
        buf ^= 1;
        if (run >= NPTS) break;     // uniform (run identical across CTA)
    }
    __syncthreads();

    int n = run;
    if (tid < 300) {
        int axis = tid / 100, pos = tid - axis * 100;
        float v = 0.0f;
        if (n > 0) {
            int j = (n >= NPTS) ? pos : (pos % n);
            v = (axis == 0) ? s0[j] : ((axis == 1) ? s1[j] : s2[j]);
        }
        g_phi[(size_t)b * 300 + tid] = v;
    }
}

// ------------------------------ hidden layer --------------------------------
// BM=16, N=128, K=300, 256 threads, grid B/16.
// K-split dual stream: half 0 -> K [0,160) (8 tiles), half 1 -> K [160,300)
// (7 tiles); each half has private double-buffered W1 tiles; smem reduction.
// Thread tile 8 rows (f32x2 pairs, broadcast A) x 2 cols.
// Dynamic smem layout (floats):
//   phiAs [300*HS] = 6000 ; w1Bs [2][2][2560] = 10240 ; ls [48]
#define HID_SMEM_FLOATS (6000 + 10240 + 48)

extern __shared__ float sm[];

__global__ void __launch_bounds__(256) hidden_kernel(
        const float* __restrict__ lt, const float* __restrict__ b1,
        const float* __restrict__ W2, const float* __restrict__ b2) {
    float* phiAs = sm;                 // [k*HS + r]
    float* w1Bs  = sm + 6000;          // [half][buf][20*128]
    float* ls    = sm + 6000 + 10240;  // [48]

    int row0 = blockIdx.x * 16;
    int tid = threadIdx.x;
    int half = tid >> 7, t = tid & 127;
    int rbase = (t >> 6) * 8;          // 2 row groups
    int c0 = (t & 63) * 2;             // 64 col pairs

    // stage phi transposed: 16 rows x 300 = 1200 float4
    for (int idx = tid; idx < 1200; idx += 256) {
        int r = idx / 75, k4 = idx - r * 75;
        float4 v = *(const float4*)&g_phi[(size_t)(row0 + r) * 300 + k4 * 4];
        phiAs[(k4 * 4 + 0) * HS + r] = v.x;
        phiAs[(k4 * 4 + 1) * HS + r] = v.y;
        phiAs[(k4 * 4 + 2) * HS + r] = v.z;
        phiAs[(k4 * 4 + 3) * HS + r] = v.w;
    }
    if (tid < 48) ls[tid] = lt[row0 * 3 + tid];

    int ntiles = half ? 7 : 8;
    int kbase  = half ? 160 : 0;
    float* myBs = w1Bs + half * 5120;

    {   // stage tile 0 of this half (640 float4, 5 per thread)
        const float4* src = (const float4*)(g_W1t + kbase * 128);
        float4* dst = (float4*)myBs;
#pragma unroll
        for (int j = 0; j < 5; j++) dst[t + j * 128] = src[t + j * 128];
    }

    ull acc[4][2];
#pragma unroll
    for (int p = 0; p < 4; p++) {
        acc[p][0] = half ? 0ull : dup2(b1[c0]);
        acc[p][1] = half ? 0ull : dup2(b1[c0 + 1]);
    }

    for (int kt = 0; kt < 8; kt++) {
        __syncthreads();
        bool active = (kt < ntiles);
        bool pre = (kt + 1 < ntiles);
        float4 pw[5];
        if (pre) {
            const float4* src = (const float4*)(g_W1t + (kbase + (kt + 1) * 20) * 128);
#pragma unroll
            for (int j = 0; j < 5; j++) pw[j] = src[t + j * 128];
        }
        if (active) {
            const float* Bc = myBs + (kt & 1) * 2560;
            int k0 = kbase + kt * 20;
#pragma unroll
            for (int kk = 0; kk < 20; kk++) {
                int k = k0 + kk;
                F4U2 a0, a1;
                a0.f4 = *(const float4*)&phiAs[k * HS + rbase];      // broadcast, aligned
                a1.f4 = *(const float4*)&phiAs[k * HS + rbase + 4];
                float2 w = *(const float2*)&Bc[kk * 128 + c0];
                ull d0 = dup2(w.x), d1 = dup2(w.y);
                ffma2(acc[0][0], a0.u2[0], d0); ffma2(acc[0][1], a0.u2[0], d1);
                ffma2(acc[1][0], a0.u2[1], d0); ffma2(acc[1][1], a0.u2[1], d1);
                ffma2(acc[2][0], a1.u2[0], d0); ffma2(acc[2][1], a1.u2[0], d1);
                ffma2(acc[3][0], a1.u2[1], d0); ffma2(acc[3][1], a1.u2[1], d1);
            }
        }
        if (pre) {
            float4* dst = (float4*)(myBs + ((kt + 1) & 1) * 2560);
#pragma unroll
            for (int j = 0; j < 5; j++) dst[t + j * 128] = pw[j];
        }
    }

    // reduction: half 1 dumps partials, half 0 adds + relu + store
    __syncthreads();
    float* red = w1Bs;                   // reuse (all tile reads done)
    if (half == 1) {
#pragma unroll
        for (int p = 0; p < 4; p++) {
            float2 v0 = unpack2(acc[p][0]);
            float2 v1 = unpack2(acc[p][1]);
            red[t * 20 + p * 4 + 0] = v0.x;
            red[t * 20 + p * 4 + 1] = v0.y;
            red[t * 20 + p * 4 + 2] = v1.x;
            red[t * 20 + p * 4 + 3] = v1.y;
        }
    }
    __syncthreads();
    if (half == 0) {
#pragma unroll
        for (int p = 0; p < 4; p++) {
            float2 v0 = unpack2(acc[p][0]);   // col c0,   rows 2p/2p+1
            float2 v1 = unpack2(acc[p][1]);   // col c0+1, rows 2p/2p+1
            float r00 = v0.x + red[t * 20 + p * 4 + 0];
            float r10 = v0.y + red[t * 20 + p * 4 + 1];
            float r01 = v1.x + red[t * 20 + p * 4 + 2];
            float r11 = v1.y + red[t * 20 + p * 4 + 3];
            size_t base = (size_t)(row0 + rbase + 2 * p) * 256 + c0;
            *(float2*)&g_h[base]       = make_float2(fmaxf(r00, 0.f), fmaxf(r01, 0.f));
            *(float2*)&g_h[base + 256] = make_float2(fmaxf(r10, 0.f), fmaxf(r11, 0.f));
        }
    }

    // l_out half: col 128+(tid&127), 8 rows per thread
    {
        int c = tid & 127, rh = (tid >> 7) * 8;
        float w0 = W2[c * 3 + 0], w1 = W2[c * 3 + 1], w2 = W2[c * 3 + 2];
        float bc = b2[c];
#pragma unroll
        for (int r = 0; r < 8; r++) {
            float v = bc + ls[(rh + r) * 3 + 0] * w0 + ls[(rh + r) * 3 + 1] * w1
                         + ls[(rh + r) * 3 + 2] * w2;
            g_h[(size_t)(row0 + rh + r) * 256 + 128 + c] = fmaxf(v, 0.f);
        }
    }
}

// ------------------------------ output layer --------------------------------
// BM=16, N=256, K=256, 256 threads, grid B/16. Thread tile 8 rows x 2 cols.
// Dynamic smem (floats): hAs [256*HS] = 5120 ; wctBs [2][16*256] = 8192.
#define OUT_SMEM_FLOATS (5120 + 8192)

__global__ void __launch_bounds__(256) out_kernel(float* __restrict__ out) {
    float* hAs   = sm;           // [k*HS + r]
    float* wctBs = sm + 5120;    // [buf][16*256]

    int row0 = blockIdx.x * 16;
    int tid = threadIdx.x;
    int rbase = (tid >> 7) * 8;      // 2 row groups
    int c2 = (tid & 127) * 2;        // 128 col pairs

    // stage h transposed: 16 rows x 256 = 1024 float4
    for (int idx = tid; idx < 1024; idx += 256) {
        int r = idx >> 6, k4 = idx & 63;
        float4 v = *(const float4*)&g_h[(size_t)(row0 + r) * 256 + k4 * 4];
        hAs[(k4 * 4 + 0) * HS + r] = v.x;
        hAs[(k4 * 4 + 1) * HS + r] = v.y;
        hAs[(k4 * 4 + 2) * HS + r] = v.z;
        hAs[(k4 * 4 + 3) * HS + r] = v.w;
    }
    {   // stage Wct tile 0 (1024 float4, 4 per thread)
        const float4* src = (const float4*)g_Wct;
        float4* dst = (float4*)wctBs;
#pragma unroll
        for (int j = 0; j < 4; j++) dst[tid + j * 256] = src[tid + j * 256];
    }

    ull acc[4][2];
#pragma unroll
    for (int p = 0; p < 4; p++) {
        acc[p][0] = dup2(g_b34[c2]);
        acc[p][1] = dup2(g_b34[c2 + 1]);
    }

    for (int kt = 0; kt < 16; kt++) {
        __syncthreads();
        float4 pw[4];
        if (kt + 1 < 16) {
            const float4* src = (const float4*)(g_Wct + (kt + 1) * 4096);
#pragma unroll
            for (int j = 0; j < 4; j++) pw[j] = src[tid + j * 256];
        }
        const float* Bc = wctBs + (kt & 1) * 4096;
        int k0 = kt * 16;
#pragma unroll
        for (int kk = 0; kk < 16; kk++) {
            int k = k0 + kk;
            F4U2 a0, a1;
            a0.f4 = *(const float4*)&hAs[k * HS + rbase];    // broadcast, aligned
            a1.f4 = *(const float4*)&hAs[k * HS + rbase + 4];
            float2 w = *(const float2*)&Bc[kk * 256 + c2];
            ull d0 = dup2(w.x), d1 = dup2(w.y);
            ffma2(acc[0][0], a0.u2[0], d0); ffma2(acc[0][1], a0.u2[0], d1);
            ffma2(acc[1][0], a0.u2[1], d0); ffma2(acc[1][1], a0.u2[1], d1);
            ffma2(acc[2][0], a1.u2[0], d0); ffma2(acc[2][1], a1.u2[0], d1);
            ffma2(acc[3][0], a1.u2[1], d0); ffma2(acc[3][1], a1.u2[1], d1);
        }
        if (kt + 1 < 16) {
            float4* dst = (float4*)(wctBs + ((kt + 1) & 1) * 4096);
#pragma unroll
            for (int j = 0; j < 4; j++) dst[tid + j * 256] = pw[j];
        }
    }

    // epilogue: coalesced float2 stores
#pragma unroll
    for (int p = 0; p < 4; p++) {
        float2 v0 = unpack2(acc[p][0]);   // col c2,   rows 2p/2p+1
        float2 v1 = unpack2(acc[p][1]);   // col c2+1, rows 2p/2p+1
        size_t base = (size_t)(row0 + rbase + 2 * p) * 256 + c2;
        *(float2*)&out[base]       = make_float2(fmaxf(v0.x, 0.f), fmaxf(v1.x, 0.f));
        *(float2*)&out[base + 256] = make_float2(fmaxf(v0.y, 0.f), fmaxf(v1.y, 0.f));
    }
}

// ------------------------------ launch --------------------------------------
extern "C" void kernel_launch(void* const* d_in, const int* in_sizes, int n_in,
                              void* d_out, int out_size) {
    const float* x  = (const float*)d_in[0];
    const float* lt = (const float*)d_in[1];
    const float* W1 = (const float*)d_in[2];
    const float* b1 = (const float*)d_in[3];
    const float* W2 = (const float*)d_in[4];
    const float* b2 = (const float*)d_in[5];
    const float* W3 = (const float*)d_in[6];
    const float* b3 = (const float*)d_in[7];
    const float* W4 = (const float*)d_in[8];
    const float* b4 = (const float*)d_in[9];
    float* out = (float*)d_out;

    int B = in_sizes[0] / (3 * P_PTS);
    if (B > MAXB) B = MAXB;

    cudaFuncSetAttribute(hidden_kernel, cudaFuncAttributeMaxDynamicSharedMemorySize,
                         HID_SMEM_FLOATS * sizeof(float));
    cudaFuncSetAttribute(out_kernel, cudaFuncAttributeMaxDynamicSharedMemorySize,
                         OUT_SMEM_FLOATS * sizeof(float));

    foveate_kernel<<<B, 512>>>(x, lt, W1, W3, W4, b3, b4);
    hidden_kernel<<<B / 16, 256, HID_SMEM_FLOATS * sizeof(float)>>>(lt, b1, W2, b2);
    out_kernel<<<B / 16, 256, OUT_SMEM_FLOATS * sizeof(float)>>>(out);
}

// round 11
// speedup vs baseline: 1.3284x; 1.0046x over previous
#include <cuda_runtime.h>
#include <cuda_bf16.h>
#include <stdint.h>

#define P_PTS   10000
#define NPTS    100
#define MAXB    4096

typedef unsigned long long ull;

// ------------------------------ scratch ------------------------------------
__device__ float g_phi [MAXB * 300];   // phi row-major [b][300]
__device__ float g_h   [MAXB * 256];   // hidden concat row-major [b][256]
__device__ float g_W1t [300 * 128];    // W1 transposed [k][c]
__device__ float g_Wct [256 * 256];    // [W3|W4] transposed [k][j]
__device__ float g_b34 [256];          // b3 + b4

// ------------------------------ f32x2 helpers -------------------------------
union F4U2 { float4 f4; ull u2[2]; float f[4]; };

__device__ __forceinline__ ull dup2(float a) {
    ull r; asm("mov.b64 %0, {%1, %1};" : "=l"(r) : "f"(a)); return r;
}
__device__ __forceinline__ void ffma2(ull& acc, ull a, ull b) {
    asm("fma.rn.f32x2 %0, %1, %2, %3;" : "=l"(acc) : "l"(a), "l"(b), "l"(acc));
}
__device__ __forceinline__ float2 unpack2(ull v) {
    float2 f; asm("mov.b64 {%0, %1}, %2;" : "=f"(f.x), "=f"(f.y) : "l"(v)); return f;
}

// ------------------------------ foveate (+ folded prep) ---------------------
// CTA-per-batch, 512 threads, 2048-pt float4 chunks, ballot-based ordered
// compaction, shfl-based cross-warp prefix (no 16-iter smem scan),
// ONE __syncthreads per chunk, early exit at 100 points.
__global__ void __launch_bounds__(512) foveate_kernel(
        const float* __restrict__ x,  const float* __restrict__ lt,
        const float* __restrict__ W1, const float* __restrict__ W3,
        const float* __restrict__ W4, const float* __restrict__ b3,
        const float* __restrict__ b4) {
    __shared__ float s0[NPTS], s1[NPTS], s2[NPTS];
    __shared__ int warp_cnt[2][16];

    int b = blockIdx.x;
    int tid = threadIdx.x, lane = tid & 31, wid = tid >> 5;

    // folded prep (independent; consumed by GEMMs)
    {
        int g = b * 512 + tid;
        if (g < 300 * 128) {
            int k = g / 128, c = g - k * 128;
            g_W1t[g] = W1[c * 300 + k];
        }
        if (g < 256 * 256) {
            int k = g >> 8, j = g & 255;
            g_Wct[g] = (k < 128) ? W3[j * 128 + k] : W4[j * 128 + (k - 128)];
        }
        if (g < 256) g_b34[g] = b3[g] + b4[g];
    }

    const float* xb = x + (size_t)b * 3 * P_PTS;
    float l0 = lt[b * 3 + 0], l1 = lt[b * 3 + 1], l2 = lt[b * 3 + 2];
    float lo0 = l0 - 0.25f, hi0 = l0 + 0.25f;
    float lo1 = l1 - 0.25f, hi1 = l1 + 0.25f;
    float lo2 = l2 - 0.25f, hi2 = l2 + 0.25f;
    unsigned ltm = (1u << lane) - 1u;

    int run = 0, buf = 0;
    for (int base = 0; base < P_PTS; base += 2048) {
        int p0 = base + tid * 4;
        float v0[4], v1[4], v2[4];
        unsigned m = 0;
        if (p0 < P_PTS) {  // P divisible by 4 -> float4 fully in or out
            float4 f0 = *(const float4*)(xb + p0);
            float4 f1 = *(const float4*)(xb + P_PTS + p0);
            float4 f2 = *(const float4*)(xb + 2 * P_PTS + p0);
            v0[0]=f0.x; v0[1]=f0.y; v0[2]=f0.z; v0[3]=f0.w;
            v1[0]=f1.x; v1[1]=f1.y; v1[2]=f1.z; v1[3]=f1.w;
            v2[0]=f2.x; v2[1]=f2.y; v2[2]=f2.z; v2[3]=f2.w;
#pragma unroll
            for (int i = 0; i < 4; i++) {
                bool in = (v0[i] >= lo0) && (v0[i] <= hi0) &&
                          (v1[i] >= lo1) && (v1[i] <= hi1) &&
                          (v2[i] >= lo2) && (v2[i] <= hi2);
                m |= ((unsigned)in) << i;
            }
        }
        unsigned bl0 = __ballot_sync(0xffffffffu,  m       & 1u);
        unsigned bl1 = __ballot_sync(0xffffffffu, (m >> 1) & 1u);
        unsigned bl2 = __ballot_sync(0xffffffffu, (m >> 2) & 1u);
        unsigned bl3 = __ballot_sync(0xffffffffu, (m >> 3) & 1u);
        if (lane == 0)
            warp_cnt[buf][wid] = __popc(bl0) + __popc(bl1) + __popc(bl2) + __popc(bl3);
        int excl = __popc(bl0 & ltm) + __popc(bl1 & ltm) +
                   __popc(bl2 & ltm) + __popc(bl3 & ltm);
        __syncthreads();

        // shfl-based prefix over 16 warp counts (redundant per warp)
        int v = (lane < 16) ? warp_cnt[buf][lane] : 0;
#pragma unroll
        for (int off = 1; off < 16; off <<= 1) {
            int t = __shfl_up_sync(0xffffffffu, v, off);
            if (lane >= off) v += t;
        }
        int tot = __shfl_sync(0xffffffffu, v, 15);
        int wsrc = (wid == 0) ? 0 : (wid - 1);
        int wofft = __shfl_sync(0xffffffffu, v, wsrc);
        int woff = (wid == 0) ? 0 : wofft;

        int r = run + woff + excl;
#pragma unroll
        for (int i = 0; i < 4; i++) {
            if ((m >> i) & 1u) {
                if (r < NPTS) { s0[r] = v0[i]; s1[r] = v1[i]; s2[r] = v2[i]; }
                r++;
            }
        }
        run += tot;
        buf ^= 1;
        if (run >= NPTS) break;     // uniform (run identical across CTA)
    }
    __syncthreads();

    int n = run;
    if (tid < 300) {
        int axis = tid / 100, pos = tid - axis * 100;
        float v = 0.0f;
        if (n > 0) {
            int j = (n >= NPTS) ? pos : (pos % n);
            v = (axis == 0) ? s0[j] : ((axis == 1) ? s1[j] : s2[j]);
        }
        g_phi[(size_t)b * 300 + tid] = v;
    }
}

// ------------------------------ hidden layer --------------------------------
// BM=32, N=128, K=300 (15 tiles of 20), 256 threads, grid B/32 = 128.
// Thread tile 8 rows (f32x2 pairs, broadcast A) x 2 cols.
// Smem (floats): phiAs [300*32]=9600 ; w1Bs [2][20*128]=5120 ; ls [96].
#define HID_SMEM_FLOATS (9600 + 5120 + 96)

extern __shared__ float sm[];

__global__ void __launch_bounds__(256, 1) hidden_kernel(
        const float* __restrict__ lt, const float* __restrict__ b1,
        const float* __restrict__ W2, const float* __restrict__ b2) {
    float* phiAs = sm;                 // [k*32 + r]
    float* w1Bs  = sm + 9600;          // [buf][20*128]
    float* ls    = sm + 9600 + 5120;   // [96]

    int row0 = blockIdx.x * 32;
    int tid = threadIdx.x;
    int rbase = (tid >> 6) * 8;        // 4 row groups of 8 (warp-uniform)
    int c0 = (tid & 63) * 2;           // 64 col pairs

    // stage phi transposed, conflict-free: r = idx&31 (lanes -> distinct rows)
    for (int idx = tid; idx < 2400; idx += 256) {
        int r = idx & 31, k4 = idx >> 5;      // k4 in 0..74
        float4 v = *(const float4*)&g_phi[(size_t)(row0 + r) * 300 + k4 * 4];
        phiAs[(k4 * 4 + 0) * 32 + r] = v.x;
        phiAs[(k4 * 4 + 1) * 32 + r] = v.y;
        phiAs[(k4 * 4 + 2) * 32 + r] = v.z;
        phiAs[(k4 * 4 + 3) * 32 + r] = v.w;
    }
    if (tid < 96) ls[tid] = lt[row0 * 3 + tid];
    // stage W1 tile 0 (640 float4)
    for (int idx = tid; idx < 640; idx += 256)
        *(float4*)&w1Bs[idx * 4] = *(const float4*)&g_W1t[idx * 4];

    ull acc[4][2];
#pragma unroll
    for (int p = 0; p < 4; p++) { acc[p][0] = dup2(b1[c0]); acc[p][1] = dup2(b1[c0 + 1]); }

    for (int kt = 0; kt < 15; kt++) {
        __syncthreads();
        float4 pw[3];
        bool pv[3] = {false, false, false};
        if (kt + 1 < 15) {
            const float* src = g_W1t + (kt + 1) * 2560;
#pragma unroll
            for (int j = 0; j < 3; j++) {
                int idx = tid + j * 256;
                if (idx < 640) { pw[j] = *(const float4*)(src + idx * 4); pv[j] = true; }
            }
        }
        const float* Bc = w1Bs + (kt & 1) * 2560;
        int k0 = kt * 20;
#pragma unroll
        for (int kk = 0; kk < 20; kk++) {
            int k = k0 + kk;
            F4U2 a0, a1;
            a0.f4 = *(const float4*)&phiAs[k * 32 + rbase];      // broadcast, aligned
            a1.f4 = *(const float4*)&phiAs[k * 32 + rbase + 4];
            float2 w = *(const float2*)&Bc[kk * 128 + c0];
            ull d0 = dup2(w.x), d1 = dup2(w.y);
            ffma2(acc[0][0], a0.u2[0], d0); ffma2(acc[0][1], a0.u2[0], d1);
            ffma2(acc[1][0], a0.u2[1], d0); ffma2(acc[1][1], a0.u2[1], d1);
            ffma2(acc[2][0], a1.u2[0], d0); ffma2(acc[2][1], a1.u2[0], d1);
            ffma2(acc[3][0], a1.u2[1], d0); ffma2(acc[3][1], a1.u2[1], d1);
        }
        if (kt + 1 < 15) {
            float* dst = w1Bs + ((kt + 1) & 1) * 2560;
#pragma unroll
            for (int j = 0; j < 3; j++) {
                int idx = tid + j * 256;
                if (pv[j]) *(float4*)(dst + idx * 4) = pw[j];
            }
        }
    }

    // epilogue: relu + coalesced float2 stores
#pragma unroll
    for (int p = 0; p < 4; p++) {
        float2 v0 = unpack2(acc[p][0]);   // col c0,   rows 2p/2p+1
        float2 v1 = unpack2(acc[p][1]);   // col c0+1, rows 2p/2p+1
        size_t base = (size_t)(row0 + rbase + 2 * p) * 256 + c0;
        *(float2*)&g_h[base]       = make_float2(fmaxf(v0.x, 0.f), fmaxf(v1.x, 0.f));
        *(float2*)&g_h[base + 256] = make_float2(fmaxf(v0.y, 0.f), fmaxf(v1.y, 0.f));
    }

    // l_out half: col 128+(tid&127), 16 rows per thread (2 row halves)
    {
        int c = tid & 127, rh = (tid >> 7) * 16;
        float w0 = W2[c * 3 + 0], w1 = W2[c * 3 + 1], w2 = W2[c * 3 + 2];
        float bc = b2[c];
#pragma unroll
        for (int r = 0; r < 16; r++) {
            float v = bc + ls[(rh + r) * 3 + 0] * w0 + ls[(rh + r) * 3 + 1] * w1
                         + ls[(rh + r) * 3 + 2] * w2;
            g_h[(size_t)(row0 + rh + r) * 256 + 128 + c] = fmaxf(v, 0.f);
        }
    }
}

// ------------------------------ output layer --------------------------------
// BM=32, N=256, K=256 (16 tiles of 16), 256 threads, grid B/32 = 128.
// Thread tile 8 rows (f32x2 pairs, broadcast A) x 4 cols.
// Smem (floats): hAs [256*32]=8192 ; wctBs [2][16*256]=8192.
#define OUT_SMEM_FLOATS (8192 + 8192)

__global__ void __launch_bounds__(256, 1) out_kernel(float* __restrict__ out) {
    float* hAs   = sm;           // [k*32 + r]
    float* wctBs = sm + 8192;    // [buf][16*256]

    int row0 = blockIdx.x * 32;
    int tid = threadIdx.x;
    int rbase = (tid >> 6) * 8;      // 4 row groups of 8 (warp-uniform)
    int c2 = (tid & 63) * 4;         // 64 col quads

    // stage h transposed, conflict-free
    for (int idx = tid; idx < 2048; idx += 256) {
        int r = idx & 31, k4 = idx >> 5;      // k4 in 0..63
        float4 v = *(const float4*)&g_h[(size_t)(row0 + r) * 256 + k4 * 4];
        hAs[(k4 * 4 + 0) * 32 + r] = v.x;
        hAs[(k4 * 4 + 1) * 32 + r] = v.y;
        hAs[(k4 * 4 + 2) * 32 + r] = v.z;
        hAs[(k4 * 4 + 3) * 32 + r] = v.w;
    }
    {   // stage Wct tile 0 (1024 float4, 4 per thread)
        const float4* src = (const float4*)g_Wct;
        float4* dst = (float4*)wctBs;
#pragma unroll
        for (int j = 0; j < 4; j++) dst[tid + j * 256] = src[tid + j * 256];
    }

    ull acc[4][4];
#pragma unroll
    for (int p = 0; p < 4; p++)
#pragma unroll
        for (int c = 0; c < 4; c++) acc[p][c] = dup2(g_b34[c2 + c]);

    for (int kt = 0; kt < 16; kt++) {
        __syncthreads();
        float4 pw[4];
        if (kt + 1 < 16) {
            const float4* src = (const float4*)(g_Wct + (kt + 1) * 4096);
#pragma unroll
            for (int j = 0; j < 4; j++) pw[j] = src[tid + j * 256];
        }
        const float* Bc = wctBs + (kt & 1) * 4096;
        int k0 = kt * 16;
#pragma unroll
        for (int kk = 0; kk < 16; kk++) {
            int k = k0 + kk;
            F4U2 a0, a1;
            a0.f4 = *(const float4*)&hAs[k * 32 + rbase];    // broadcast, aligned
            a1.f4 = *(const float4*)&hAs[k * 32 + rbase + 4];
            F4U2 w; w.f4 = *(const float4*)&Bc[kk * 256 + c2];
#pragma unroll
            for (int c = 0; c < 4; c++) {
                ull d = dup2(w.f[c]);
                ffma2(acc[0][c], a0.u2[0], d);
                ffma2(acc[1][c], a0.u2[1], d);
                ffma2(acc[2][c], a1.u2[0], d);
                ffma2(acc[3][c], a1.u2[1], d);
            }
        }
        if (kt + 1 < 16) {
            float4* dst = (float4*)(wctBs + ((kt + 1) & 1) * 4096);
#pragma unroll
            for (int j = 0; j < 4; j++) dst[tid + j * 256] = pw[j];
        }
    }

    // epilogue: relu + coalesced float4 stores
#pragma unroll
    for (int p = 0; p < 4; p++) {
        float2 vc[4];
#pragma unroll
        for (int c = 0; c < 4; c++) vc[c] = unpack2(acc[p][c]);
        float4 o0, o1;
        o0.x = fmaxf(vc[0].x, 0.f); o0.y = fmaxf(vc[1].x, 0.f);
        o0.z = fmaxf(vc[2].x, 0.f); o0.w = fmaxf(vc[3].x, 0.f);
        o1.x = fmaxf(vc[0].y, 0.f); o1.y = fmaxf(vc[1].y, 0.f);
        o1.z = fmaxf(vc[2].y, 0.f); o1.w = fmaxf(vc[3].y, 0.f);
        size_t base = (size_t)(row0 + rbase + 2 * p) * 256 + c2;
        *(float4*)&out[base]       = o0;
        *(float4*)&out[base + 256] = o1;
    }
}

// ------------------------------ launch --------------------------------------
extern "C" void kernel_launch(void* const* d_in, const int* in_sizes, int n_in,
                              void* d_out, int out_size) {
    const float* x  = (const float*)d_in[0];
    const float* lt = (const float*)d_in[1];
    const float* W1 = (const float*)d_in[2];
    const float* b1 = (const float*)d_in[3];
    const float* W2 = (const float*)d_in[4];
    const float* b2 = (const float*)d_in[5];
    const float* W3 = (const float*)d_in[6];
    const float* b3 = (const float*)d_in[7];
    const float* W4 = (const float*)d_in[8];
    const float* b4 = (const float*)d_in[9];
    float* out = (float*)d_out;

    int B = in_sizes[0] / (3 * P_PTS);
    if (B > MAXB) B = MAXB;

    cudaFuncSetAttribute(hidden_kernel, cudaFuncAttributeMaxDynamicSharedMemorySize,
                         HID_SMEM_FLOATS * sizeof(float));
    cudaFuncSetAttribute(out_kernel, cudaFuncAttributeMaxDynamicSharedMemorySize,
                         OUT_SMEM_FLOATS * sizeof(float));

    foveate_kernel<<<B, 512>>>(x, lt, W1, W3, W4, b3, b4);
    hidden_kernel<<<B / 32, 256, HID_SMEM_FLOATS * sizeof(float)>>>(lt, b1, W2, b2);
    out_kernel<<<B / 32, 256, OUT_SMEM_FLOATS * sizeof(float)>>>(out);
}